// round 16
// baseline (speedup 1.0000x reference)
#include <cuda_runtime.h>
#include <cuda_bf16.h>
#include <cuda_fp16.h>
#include <stdint.h>
#include <math.h>

// Problem constants
#define BB 16
#define TT 128
#define DD 8192           // C*H*W
#define FF 16             // NUM_FEAT
#define GG 4096           // NUM_FEAT*H*W
#define MM (BB*TT)        // 2048 rows

// ---------------- scratch (device globals; no allocs allowed) ----------------
__device__ float g_q[MM * FF];
__device__ float g_k[MM * FF];
__device__ __half g_attnh[BB * TT * TT];    // attn fp16 [b][t][s], 512 KB
__device__ float g_rs[MM];
__device__ __half g_yh[(size_t)MM * DD];    // 32 MB, row-major [m][k], fp16
__device__ __half g_w3h[(size_t)GG * DD];   // 64 MB, row-major [n][k], fp16

// ======================= PTX helpers (compute_103-safe) ======================
__device__ __forceinline__ uint32_t smem_u32(const void* p) {
    uint32_t a;
    asm("{ .reg .u64 t; cvta.to.shared.u64 t, %1; cvt.u32.u64 %0, t; }" : "=r"(a) : "l"(p));
    return a;
}
__device__ __forceinline__ void cp_async16(uint32_t dst, const void* src) {
    asm volatile("cp.async.cg.shared.global [%0], [%1], 16;" :: "r"(dst), "l"(src) : "memory");
}
#define CP_COMMIT() asm volatile("cp.async.commit_group;" ::: "memory")
#define CP_WAIT1()  asm volatile("cp.async.wait_group 1;" ::: "memory")
#define CP_WAIT2()  asm volatile("cp.async.wait_group 2;" ::: "memory")
#define CP_WAIT0()  asm volatile("cp.async.wait_group 0;" ::: "memory")

__device__ __forceinline__ void ldsm4(uint32_t* r, uint32_t addr) {
    asm volatile("ldmatrix.sync.aligned.m8n8.x4.shared.b16 {%0,%1,%2,%3}, [%4];"
        : "=r"(r[0]), "=r"(r[1]), "=r"(r[2]), "=r"(r[3]) : "r"(addr));
}
__device__ __forceinline__ void ldsm4t(uint32_t* r, uint32_t addr) {
    asm volatile("ldmatrix.sync.aligned.m8n8.x4.trans.shared.b16 {%0,%1,%2,%3}, [%4];"
        : "=r"(r[0]), "=r"(r[1]), "=r"(r[2]), "=r"(r[3]) : "r"(addr));
}
__device__ __forceinline__ void mma16816h(float* d, const uint32_t* a, uint32_t b0, uint32_t b1) {
    asm volatile("mma.sync.aligned.m16n8k16.row.col.f32.f16.f16.f32 "
        "{%0,%1,%2,%3}, {%4,%5,%6,%7}, {%8,%9}, {%0,%1,%2,%3};"
        : "+f"(d[0]), "+f"(d[1]), "+f"(d[2]), "+f"(d[3])
        : "r"(a[0]), "r"(a[1]), "r"(a[2]), "r"(a[3]), "r"(b0), "r"(b1));
}
__device__ __forceinline__ float dot4(float4 a, float4 b) {
    return a.x * b.x + a.y * b.y + a.z * b.z + a.w * b.w;
}

// =============================================================================
// K1: q/k projection (unchanged)
// =============================================================================
#define QK_SMEM (69632 + 32768)

__global__ __launch_bounds__(256) void k_qk(
    const float* __restrict__ x1, const float* __restrict__ x2,
    const float* __restrict__ w1, const float* __restrict__ b1,
    const float* __restrict__ w2, const float* __restrict__ b2)
{
    extern __shared__ char smq[];
    const uint32_t sb = smem_u32(smq);
    float* red = (float*)(smq + 69632);

    const int tid  = threadIdx.x;
    const int ksl  = tid >> 4;
    const int rgrp = (tid >> 2) & 3;
    const int fgrp = tid & 3;
    const int row0 = blockIdx.x * 16;

    auto issue = [&](int k0, int stg) {
        uint32_t base = sb + stg * 34816;
        #pragma unroll
        for (int i = 0; i < 8; ++i) {
            int id  = tid + i * 256;
            int a   = id >> 9;
            int rem = id & 511;
            int r   = rem >> 5;
            int c   = rem & 31;
            uint32_t dst = base + a * 8704 + r * 544 + c * 16;
            const float* s;
            if      (a == 0) s = x1 + (size_t)(row0 + r) * DD + k0 + c * 4;
            else if (a == 1) s = x2 + (size_t)(row0 + r) * DD + k0 + c * 4;
            else if (a == 2) s = w1 + (size_t)r * DD + k0 + c * 4;
            else             s = w2 + (size_t)r * DD + k0 + c * 4;
            cp_async16(dst, s);
        }
    };

    float accq[4][4], acck[4][4];
    #pragma unroll
    for (int i = 0; i < 4; ++i)
        #pragma unroll
        for (int j = 0; j < 4; ++j) { accq[i][j] = 0.f; acck[i][j] = 0.f; }

    issue(0, 0);   CP_COMMIT();
    issue(128, 1); CP_COMMIT();

    const int kb = ksl * 8;
    for (int c = 0; c < 64; ++c) {
        CP_WAIT1();
        __syncthreads();

        const char* st = smq + (c & 1) * 34816;
        const float* X1s = (const float*)st;
        const float* X2s = (const float*)(st + 8704);
        const float* W1s = (const float*)(st + 17408);
        const float* W2s = (const float*)(st + 26112);

        #pragma unroll
        for (int u4 = 0; u4 < 8; u4 += 4) {
            float4 xv[4], wv[4];
            #pragma unroll
            for (int i = 0; i < 4; ++i)
                xv[i] = *(const float4*)&X1s[(rgrp * 4 + i) * 136 + kb + u4];
            #pragma unroll
            for (int j = 0; j < 4; ++j)
                wv[j] = *(const float4*)&W1s[(fgrp * 4 + j) * 136 + kb + u4];
            #pragma unroll
            for (int i = 0; i < 4; ++i)
                #pragma unroll
                for (int j = 0; j < 4; ++j)
                    accq[i][j] += dot4(xv[i], wv[j]);

            #pragma unroll
            for (int i = 0; i < 4; ++i)
                xv[i] = *(const float4*)&X2s[(rgrp * 4 + i) * 136 + kb + u4];
            #pragma unroll
            for (int j = 0; j < 4; ++j)
                wv[j] = *(const float4*)&W2s[(fgrp * 4 + j) * 136 + kb + u4];
            #pragma unroll
            for (int i = 0; i < 4; ++i)
                #pragma unroll
                for (int j = 0; j < 4; ++j)
                    acck[i][j] += dot4(xv[i], wv[j]);
        }
        __syncthreads();
        if (c + 2 < 64) issue((c + 2) * 128, c & 1);
        CP_COMMIT();
    }

    #pragma unroll
    for (int i = 0; i < 4; ++i)
        #pragma unroll
        for (int j = 0; j < 4; ++j) {
            int rf = (rgrp * 4 + i) * 16 + fgrp * 4 + j;
            red[rf * 16 + ksl]        = accq[i][j];
            red[4096 + rf * 16 + ksl] = acck[i][j];
        }
    __syncthreads();

    #pragma unroll
    for (int o = tid; o < 512; o += 256) {
        const int sd = o >> 8, r = (o >> 4) & 15, f = o & 15;
        const float* p = red + sd * 4096 + (r * 16 + f) * 16;
        float s = 0.f;
        #pragma unroll
        for (int q8 = 0; q8 < 16; ++q8) s += p[q8];
        if (sd == 0) g_q[(row0 + r) * FF + f] = s + b1[f];
        else         g_k[(row0 + r) * FF + f] = s + b2[f];
    }
}

// =============================================================================
// K2: scores + softmax over t (axis=1) + rowsums; attn stored as fp16
// =============================================================================
__global__ __launch_bounds__(128) void k_scores_softmax()
{
    __shared__ float qs[TT][17];
    __shared__ float redp[4][TT];

    const int b = blockIdx.x;
    const int s = threadIdx.x;
    const int lane = s & 31, wid = s >> 5;

    #pragma unroll
    for (int i = 0; i < 16; ++i) {
        int lin = s + i * 128;
        int t = lin >> 4, f = lin & 15;
        qs[t][f] = g_q[(b * TT + t) * FF + f];
    }
    float kr[FF];
    #pragma unroll
    for (int j = 0; j < FF; ++j) kr[j] = g_k[(b * TT + s) * FF + j];
    __syncthreads();

    float m = -1e30f, l = 0.f;
    for (int t = 0; t < TT; ++t) {
        float sc = 0.f;
        #pragma unroll
        for (int j = 0; j < FF; ++j) sc += qs[t][j] * kr[j];
        float nm = fmaxf(m, sc);
        l = l * expf(m - nm) + expf(sc - nm);
        m = nm;
    }
    float inv = 1.f / l;

    for (int t = 0; t < TT; ++t) {
        float sc = 0.f;
        #pragma unroll
        for (int j = 0; j < FF; ++j) sc += qs[t][j] * kr[j];
        float a = expf(sc - m) * inv;
        g_attnh[(b * TT + t) * TT + s] = __float2half_rn(a);

        float v = a;
        #pragma unroll
        for (int off = 16; off > 0; off >>= 1)
            v += __shfl_down_sync(0xffffffffu, v, off);
        if (lane == 0) redp[wid][t] = v;
    }
    __syncthreads();
    if (s < TT)
        g_rs[b * TT + s] = redp[0][s] + redp[1][s] + redp[2][s] + redp[3][s];
}

// =============================================================================
// K3: fused y = attn @ x1 HMMA [blocks 0..1023] + w3 fp32->fp16 [1024..1535]
// =============================================================================
#define SMEM_KY 65536
#define NSPLIT 512

__global__ __launch_bounds__(256) void k_y(
    const float* __restrict__ x1, const float* __restrict__ w3)
{
    const int tid = threadIdx.x;

    if (blockIdx.x >= 1024) {
        const size_t stride = (size_t)NSPLIT * 256;
        const size_t base   = (size_t)(blockIdx.x - 1024) * 256 + tid;
        const float4* src = (const float4*)w3;
        #pragma unroll 1
        for (int it = 0; it < 16; ++it) {
            size_t i0 = base + (size_t)it * 4 * stride;
            float4 v[4];
            #pragma unroll
            for (int u = 0; u < 4; ++u) v[u] = src[i0 + u * stride];
            #pragma unroll
            for (int u = 0; u < 4; ++u) {
                __half2 h0, h1;
                h0.x = __float2half_rn(v[u].x); h0.y = __float2half_rn(v[u].y);
                h1.x = __float2half_rn(v[u].z); h1.y = __float2half_rn(v[u].w);
                uint2 hu; hu.x = *(uint32_t*)&h0; hu.y = *(uint32_t*)&h1;
                *(uint2*)&g_w3h[(i0 + u * stride) * 4] = hu;
            }
        }
        return;
    }

    extern __shared__ char smy[];
    const uint32_t sA = smem_u32(smy);
    const uint32_t sX = sA + 32768;

    const int lane = tid & 31;
    const int wid  = tid >> 5;
    const int wm   = wid & 1;
    const int wn   = wid >> 1;
    const int dt   = blockIdx.x & 63;
    const int b    = blockIdx.x >> 6;

    #pragma unroll
    for (int i = 0; i < 8; ++i) {
        int id = tid + i * 256;
        int s = id >> 4, c = id & 15;
        cp_async16(sA + s * 256 + ((c ^ (s & 7)) << 4),
                   g_attnh + (size_t)(b * TT + s) * TT + c * 8);
    }
    CP_COMMIT();

    #pragma unroll
    for (int i = 0; i < 16; ++i) {
        int id = tid + i * 256;
        int s = id >> 5, q = id & 31;
        float4 v = *(const float4*)&x1[(size_t)(b * TT + s) * DD + dt * 128 + q * 4];
        __half2 p0, p1;
        p0.x = __float2half_rn(v.x); p0.y = __float2half_rn(v.y);
        p1.x = __float2half_rn(v.z); p1.y = __float2half_rn(v.w);
        uint2 u; u.x = *(uint32_t*)&p0; u.y = *(uint32_t*)&p1;
        int c = q >> 1, h = q & 1;
        *(uint2*)(smy + 32768 + s * 256 + ((c ^ (s & 7)) << 4) + h * 8) = u;
    }
    CP_WAIT0();
    __syncthreads();

    float acc[4][4][4];
    #pragma unroll
    for (int a = 0; a < 4; ++a)
        #pragma unroll
        for (int bq = 0; bq < 4; ++bq)
            #pragma unroll
            for (int c = 0; c < 4; ++c) acc[a][bq][c] = 0.f;

    const int r_lane = (lane & 7) + ((lane >> 3) & 1) * 8;
    const int c_lane = lane >> 4;

    #pragma unroll
    for (int s16 = 0; s16 < 8; ++s16) {
        uint32_t af[4][4];
        #pragma unroll
        for (int mf = 0; mf < 4; ++mf) {
            int t = wm * 64 + mf * 16 + r_lane;
            int c = s16 * 2 + c_lane;
            ldsm4(af[mf], sA + t * 256 + ((c ^ (t & 7)) << 4));
        }
        #pragma unroll
        for (int nf2 = 0; nf2 < 2; ++nf2) {
            int srow = s16 * 16 + r_lane;
            int c = wn * 4 + nf2 * 2 + c_lane;
            uint32_t bt[4];
            ldsm4t(bt, sX + srow * 256 + ((c ^ (srow & 7)) << 4));
            #pragma unroll
            for (int mf = 0; mf < 4; ++mf) {
                mma16816h(acc[mf][nf2 * 2 + 0], af[mf], bt[0], bt[1]);
                mma16816h(acc[mf][nf2 * 2 + 1], af[mf], bt[2], bt[3]);
            }
        }
    }

    const int r_ep  = lane >> 2;
    const int cpair = (lane & 3) * 2;
    #pragma unroll
    for (int mf = 0; mf < 4; ++mf) {
        #pragma unroll
        for (int nf = 0; nf < 4; ++nf) {
            int t = wm * 64 + mf * 16 + r_ep;
            int d = dt * 128 + wn * 32 + nf * 8 + cpair;
            __half2 h0, h1;
            h0.x = __float2half_rn(acc[mf][nf][0]);
            h0.y = __float2half_rn(acc[mf][nf][1]);
            h1.x = __float2half_rn(acc[mf][nf][2]);
            h1.y = __float2half_rn(acc[mf][nf][3]);
            *(__half2*)&g_yh[(size_t)(b * TT + t) * DD + d]       = h0;
            *(__half2*)&g_yh[(size_t)(b * TT + t + 8) * DD + d]   = h1;
        }
    }
}

// =============================================================================
// K4 v5: out[m,g] = sum_k y[m,k] w3[g,k] + rs[m] b3[g]
// 128x128 tile, 128 threads (4 warps, 2m x 2n), warp tile 64x64:
// ldsm redundancy A x2 + B x2 (32KB/CTA/kt vs 48KB before), 8 ldsm -> 32 MMA
// per ks. acc=128 regs, launch_bounds(128,2) -> 256-reg cap, no spills.
// 2 CTAs/SM, NSTG=4 x 16KB = 64KB smem, single-sync mainloop.
// =============================================================================
#define STAGE_BYTES 16384
#define NSTG 4
#define SMEM_K4 (NSTG * STAGE_BYTES)
#define OFF_B 8192

__global__ __launch_bounds__(128, 2) void k_out_tc(
    const float* __restrict__ b3, float* __restrict__ out)
{
    extern __shared__ char smem[];
    const uint32_t sb = smem_u32(smem);
    const int tid  = threadIdx.x;
    const int lane = tid & 31;
    const int wid  = tid >> 5;
    const int wm   = wid & 1;          // 2 warps in m (64 rows each)
    const int wn   = wid >> 1;         // 2 warps in n (64 cols each)
    const int rb   = blockIdx.x;       // M tile (0..15) -> 128 rows
    const int nb   = blockIdx.y;       // N tile (0..31) -> 128 cols

    const __half* aP = g_yh  + (size_t)rb * 128 * DD;
    const __half* bP = g_w3h + (size_t)nb * 128 * DD;

    // loader: 8 x 16B chunks per thread per stage (A: 4, B: 4)
    auto issue_stage = [&](int kt, int stage) {
        const uint32_t sbase = sb + stage * STAGE_BYTES;
        #pragma unroll
        for (int i = 0; i < 4; ++i) {
            const int id = i * 128 + tid;
            const int r  = id >> 2;
            const int c  = id & 3;
            uint32_t dst = sbase + r * 64 + ((c ^ ((r >> 1) & 3)) << 4);
            cp_async16(dst, aP + (size_t)r * DD + kt * 32 + c * 8);
        }
        #pragma unroll
        for (int i = 0; i < 4; ++i) {
            const int id = i * 128 + tid;
            const int r  = id >> 2;
            const int c  = id & 3;
            uint32_t dst = sbase + OFF_B + r * 64 + ((c ^ ((r >> 1) & 3)) << 4);
            cp_async16(dst, bP + (size_t)r * DD + kt * 32 + c * 8);
        }
    };

    float acc[4][8][4];                 // [mf][nf8][frag] = 128 regs
    #pragma unroll
    for (int a = 0; a < 4; ++a)
        #pragma unroll
        for (int b2 = 0; b2 < 8; ++b2)
            #pragma unroll
            for (int c = 0; c < 4; ++c) acc[a][b2][c] = 0.f;

    const int r_lane = (lane & 7) + ((lane >> 3) & 1) * 8;
    const int c_lane = lane >> 4;

    int rA64[4], rAx[4], rB64[4], rBx[4];
    #pragma unroll
    for (int f = 0; f < 4; ++f) {
        int ra = wm * 64 + f * 16 + r_lane;
        rA64[f] = ra * 64; rAx[f] = (ra >> 1) & 3;
        int rn = wn * 64 + f * 16 + r_lane;
        rB64[f] = rn * 64; rBx[f] = (rn >> 1) & 3;
    }

    issue_stage(0, 0); CP_COMMIT();
    issue_stage(1, 1); CP_COMMIT();
    issue_stage(2, 2); CP_COMMIT();

    const int KT = DD / 32;
    for (int kt = 0; kt < KT; ++kt) {
        CP_WAIT2();
        __syncthreads();

        const uint32_t sbase = sb + (kt & (NSTG - 1)) * STAGE_BYTES;
        #pragma unroll
        for (int ks = 0; ks < 2; ++ks) {
            const int cbase = 2 * ks + c_lane;
            uint32_t af[4][4], bf[4][4];
            // one contiguous 8-ldsm burst
            #pragma unroll
            for (int mf = 0; mf < 4; ++mf)
                ldsm4(af[mf], sbase + rA64[mf] + ((cbase ^ rAx[mf]) << 4));
            #pragma unroll
            for (int nf = 0; nf < 4; ++nf)
                ldsm4(bf[nf], sbase + OFF_B + rB64[nf] + ((cbase ^ rBx[nf]) << 4));
            // 32 independent MMAs
            #pragma unroll
            for (int nf = 0; nf < 4; ++nf) {
                #pragma unroll
                for (int mf = 0; mf < 4; ++mf) {
                    #pragma unroll
                    for (int s = 0; s < 2; ++s)
                        mma16816h(acc[mf][nf * 2 + s], af[mf], bf[nf][s], bf[nf][s + 2]);
                }
            }
        }
        if (kt + 3 < KT) { issue_stage(kt + 3, (kt + 3) & (NSTG - 1)); }
        CP_COMMIT();
    }

    // ---- epilogue: out = acc + rs[m]*b3[g] ----
    const int r_ep  = lane >> 2;
    const int cpair = (lane & 3) * 2;

    float rsv[4][2];
    #pragma unroll
    for (int mf = 0; mf < 4; ++mf) {
        int row = rb * 128 + wm * 64 + mf * 16 + r_ep;
        rsv[mf][0] = g_rs[row];
        rsv[mf][1] = g_rs[row + 8];
    }
    float b3v[8][2];
    #pragma unroll
    for (int nf = 0; nf < 8; ++nf) {
        int colg = nb * 128 + wn * 64 + nf * 8 + cpair;
        b3v[nf][0] = b3[colg];
        b3v[nf][1] = b3[colg + 1];
    }

    #pragma unroll
    for (int mf = 0; mf < 4; ++mf) {
        #pragma unroll
        for (int nf = 0; nf < 8; ++nf) {
            int row  = rb * 128 + wm * 64 + mf * 16 + r_ep;
            int colg = nb * 128 + wn * 64 + nf * 8 + cpair;
            float2 v0, v1;
            v0.x = acc[mf][nf][0] + rsv[mf][0] * b3v[nf][0];
            v0.y = acc[mf][nf][1] + rsv[mf][0] * b3v[nf][1];
            v1.x = acc[mf][nf][2] + rsv[mf][1] * b3v[nf][0];
            v1.y = acc[mf][nf][3] + rsv[mf][1] * b3v[nf][1];
            *(float2*)&out[(size_t)row * GG + colg]       = v0;
            *(float2*)&out[(size_t)(row + 8) * GG + colg] = v1;
        }
    }
}

// =============================================================================
extern "C" void kernel_launch(void* const* d_in, const int* in_sizes, int n_in,
                              void* d_out, int out_size)
{
    const float* x1 = (const float*)d_in[0];
    const float* x2 = (const float*)d_in[1];
    const float* w1 = (const float*)d_in[2];
    const float* b1 = (const float*)d_in[3];
    const float* w2 = (const float*)d_in[4];
    const float* b2 = (const float*)d_in[5];
    const float* w3 = (const float*)d_in[6];
    const float* b3 = (const float*)d_in[7];
    float* out = (float*)d_out;

    cudaFuncSetAttribute(k_out_tc, cudaFuncAttributeMaxDynamicSharedMemorySize, SMEM_K4);
    cudaFuncSetAttribute(k_y, cudaFuncAttributeMaxDynamicSharedMemorySize, SMEM_KY);
    cudaFuncSetAttribute(k_qk, cudaFuncAttributeMaxDynamicSharedMemorySize, QK_SMEM);

    k_qk<<<MM / 16, 256, QK_SMEM>>>(x1, x2, w1, b1, w2, b2);
    k_scores_softmax<<<BB, 128>>>();
    k_y<<<1024 + NSPLIT, 256, SMEM_KY>>>(x1, w3);
    k_out_tc<<<dim3(MM / 128, GG / 128), 128, SMEM_K4>>>(b3, out);
}

// round 17
// speedup vs baseline: 1.0676x; 1.0676x over previous
#include <cuda_runtime.h>
#include <cuda_bf16.h>
#include <cuda_fp16.h>
#include <stdint.h>
#include <math.h>

// Problem constants
#define BB 16
#define TT 128
#define DD 8192           // C*H*W
#define FF 16             // NUM_FEAT
#define GG 4096           // NUM_FEAT*H*W
#define MM (BB*TT)        // 2048 rows

// ---------------- scratch (device globals; no allocs allowed) ----------------
__device__ float g_q[MM * FF];
__device__ float g_k[MM * FF];
__device__ __half g_attnh[BB * TT * TT];    // attn fp16 [b][t][s], 512 KB
__device__ float g_rs[MM];
__device__ __half g_yh[(size_t)MM * DD];    // 32 MB, row-major [m][k], fp16
__device__ __half g_w3h[(size_t)GG * DD];   // 64 MB, row-major [n][k], fp16

// ======================= PTX helpers (compute_103-safe) ======================
__device__ __forceinline__ uint32_t smem_u32(const void* p) {
    uint32_t a;
    asm("{ .reg .u64 t; cvta.to.shared.u64 t, %1; cvt.u32.u64 %0, t; }" : "=r"(a) : "l"(p));
    return a;
}
__device__ __forceinline__ void cp_async16(uint32_t dst, const void* src) {
    asm volatile("cp.async.cg.shared.global [%0], [%1], 16;" :: "r"(dst), "l"(src) : "memory");
}
#define CP_COMMIT() asm volatile("cp.async.commit_group;" ::: "memory")
#define CP_WAIT1()  asm volatile("cp.async.wait_group 1;" ::: "memory")
#define CP_WAIT2()  asm volatile("cp.async.wait_group 2;" ::: "memory")
#define CP_WAIT0()  asm volatile("cp.async.wait_group 0;" ::: "memory")

__device__ __forceinline__ void ldsm4(uint32_t* r, uint32_t addr) {
    asm volatile("ldmatrix.sync.aligned.m8n8.x4.shared.b16 {%0,%1,%2,%3}, [%4];"
        : "=r"(r[0]), "=r"(r[1]), "=r"(r[2]), "=r"(r[3]) : "r"(addr));
}
__device__ __forceinline__ void ldsm4t(uint32_t* r, uint32_t addr) {
    asm volatile("ldmatrix.sync.aligned.m8n8.x4.trans.shared.b16 {%0,%1,%2,%3}, [%4];"
        : "=r"(r[0]), "=r"(r[1]), "=r"(r[2]), "=r"(r[3]) : "r"(addr));
}
__device__ __forceinline__ void mma16816h(float* d, const uint32_t* a, uint32_t b0, uint32_t b1) {
    asm volatile("mma.sync.aligned.m16n8k16.row.col.f32.f16.f16.f32 "
        "{%0,%1,%2,%3}, {%4,%5,%6,%7}, {%8,%9}, {%0,%1,%2,%3};"
        : "+f"(d[0]), "+f"(d[1]), "+f"(d[2]), "+f"(d[3])
        : "r"(a[0]), "r"(a[1]), "r"(a[2]), "r"(a[3]), "r"(b0), "r"(b1));
}
__device__ __forceinline__ float dot4(float4 a, float4 b) {
    return a.x * b.x + a.y * b.y + a.z * b.z + a.w * b.w;
}

// =============================================================================
// K1: q/k projection (unchanged)
// =============================================================================
#define QK_SMEM (69632 + 32768)

__global__ __launch_bounds__(256) void k_qk(
    const float* __restrict__ x1, const float* __restrict__ x2,
    const float* __restrict__ w1, const float* __restrict__ b1,
    const float* __restrict__ w2, const float* __restrict__ b2)
{
    extern __shared__ char smq[];
    const uint32_t sb = smem_u32(smq);
    float* red = (float*)(smq + 69632);

    const int tid  = threadIdx.x;
    const int ksl  = tid >> 4;
    const int rgrp = (tid >> 2) & 3;
    const int fgrp = tid & 3;
    const int row0 = blockIdx.x * 16;

    auto issue = [&](int k0, int stg) {
        uint32_t base = sb + stg * 34816;
        #pragma unroll
        for (int i = 0; i < 8; ++i) {
            int id  = tid + i * 256;
            int a   = id >> 9;
            int rem = id & 511;
            int r   = rem >> 5;
            int c   = rem & 31;
            uint32_t dst = base + a * 8704 + r * 544 + c * 16;
            const float* s;
            if      (a == 0) s = x1 + (size_t)(row0 + r) * DD + k0 + c * 4;
            else if (a == 1) s = x2 + (size_t)(row0 + r) * DD + k0 + c * 4;
            else if (a == 2) s = w1 + (size_t)r * DD + k0 + c * 4;
            else             s = w2 + (size_t)r * DD + k0 + c * 4;
            cp_async16(dst, s);
        }
    };

    float accq[4][4], acck[4][4];
    #pragma unroll
    for (int i = 0; i < 4; ++i)
        #pragma unroll
        for (int j = 0; j < 4; ++j) { accq[i][j] = 0.f; acck[i][j] = 0.f; }

    issue(0, 0);   CP_COMMIT();
    issue(128, 1); CP_COMMIT();

    const int kb = ksl * 8;
    for (int c = 0; c < 64; ++c) {
        CP_WAIT1();
        __syncthreads();

        const char* st = smq + (c & 1) * 34816;
        const float* X1s = (const float*)st;
        const float* X2s = (const float*)(st + 8704);
        const float* W1s = (const float*)(st + 17408);
        const float* W2s = (const float*)(st + 26112);

        #pragma unroll
        for (int u4 = 0; u4 < 8; u4 += 4) {
            float4 xv[4], wv[4];
            #pragma unroll
            for (int i = 0; i < 4; ++i)
                xv[i] = *(const float4*)&X1s[(rgrp * 4 + i) * 136 + kb + u4];
            #pragma unroll
            for (int j = 0; j < 4; ++j)
                wv[j] = *(const float4*)&W1s[(fgrp * 4 + j) * 136 + kb + u4];
            #pragma unroll
            for (int i = 0; i < 4; ++i)
                #pragma unroll
                for (int j = 0; j < 4; ++j)
                    accq[i][j] += dot4(xv[i], wv[j]);

            #pragma unroll
            for (int i = 0; i < 4; ++i)
                xv[i] = *(const float4*)&X2s[(rgrp * 4 + i) * 136 + kb + u4];
            #pragma unroll
            for (int j = 0; j < 4; ++j)
                wv[j] = *(const float4*)&W2s[(fgrp * 4 + j) * 136 + kb + u4];
            #pragma unroll
            for (int i = 0; i < 4; ++i)
                #pragma unroll
                for (int j = 0; j < 4; ++j)
                    acck[i][j] += dot4(xv[i], wv[j]);
        }
        __syncthreads();
        if (c + 2 < 64) issue((c + 2) * 128, c & 1);
        CP_COMMIT();
    }

    #pragma unroll
    for (int i = 0; i < 4; ++i)
        #pragma unroll
        for (int j = 0; j < 4; ++j) {
            int rf = (rgrp * 4 + i) * 16 + fgrp * 4 + j;
            red[rf * 16 + ksl]        = accq[i][j];
            red[4096 + rf * 16 + ksl] = acck[i][j];
        }
    __syncthreads();

    #pragma unroll
    for (int o = tid; o < 512; o += 256) {
        const int sd = o >> 8, r = (o >> 4) & 15, f = o & 15;
        const float* p = red + sd * 4096 + (r * 16 + f) * 16;
        float s = 0.f;
        #pragma unroll
        for (int q8 = 0; q8 < 16; ++q8) s += p[q8];
        if (sd == 0) g_q[(row0 + r) * FF + f] = s + b1[f];
        else         g_k[(row0 + r) * FF + f] = s + b2[f];
    }
}

// =============================================================================
// K2: scores + softmax over t (axis=1) + rowsums; attn stored as fp16
// =============================================================================
__global__ __launch_bounds__(128) void k_scores_softmax()
{
    __shared__ float qs[TT][17];
    __shared__ float redp[4][TT];

    const int b = blockIdx.x;
    const int s = threadIdx.x;
    const int lane = s & 31, wid = s >> 5;

    #pragma unroll
    for (int i = 0; i < 16; ++i) {
        int lin = s + i * 128;
        int t = lin >> 4, f = lin & 15;
        qs[t][f] = g_q[(b * TT + t) * FF + f];
    }
    float kr[FF];
    #pragma unroll
    for (int j = 0; j < FF; ++j) kr[j] = g_k[(b * TT + s) * FF + j];
    __syncthreads();

    float m = -1e30f, l = 0.f;
    for (int t = 0; t < TT; ++t) {
        float sc = 0.f;
        #pragma unroll
        for (int j = 0; j < FF; ++j) sc += qs[t][j] * kr[j];
        float nm = fmaxf(m, sc);
        l = l * expf(m - nm) + expf(sc - nm);
        m = nm;
    }
    float inv = 1.f / l;

    for (int t = 0; t < TT; ++t) {
        float sc = 0.f;
        #pragma unroll
        for (int j = 0; j < FF; ++j) sc += qs[t][j] * kr[j];
        float a = expf(sc - m) * inv;
        g_attnh[(b * TT + t) * TT + s] = __float2half_rn(a);

        float v = a;
        #pragma unroll
        for (int off = 16; off > 0; off >>= 1)
            v += __shfl_down_sync(0xffffffffu, v, off);
        if (lane == 0) redp[wid][t] = v;
    }
    __syncthreads();
    if (s < TT)
        g_rs[b * TT + s] = redp[0][s] + redp[1][s] + redp[2][s] + redp[3][s];
}

// =============================================================================
// K3: fused y = attn @ x1 HMMA [blocks 0..1023] + w3 fp32->fp16 [1024..1535]
// =============================================================================
#define SMEM_KY 65536
#define NSPLIT 512

__global__ __launch_bounds__(256) void k_y(
    const float* __restrict__ x1, const float* __restrict__ w3)
{
    const int tid = threadIdx.x;

    if (blockIdx.x >= 1024) {
        const size_t stride = (size_t)NSPLIT * 256;
        const size_t base   = (size_t)(blockIdx.x - 1024) * 256 + tid;
        const float4* src = (const float4*)w3;
        #pragma unroll 1
        for (int it = 0; it < 16; ++it) {
            size_t i0 = base + (size_t)it * 4 * stride;
            float4 v[4];
            #pragma unroll
            for (int u = 0; u < 4; ++u) v[u] = src[i0 + u * stride];
            #pragma unroll
            for (int u = 0; u < 4; ++u) {
                __half2 h0, h1;
                h0.x = __float2half_rn(v[u].x); h0.y = __float2half_rn(v[u].y);
                h1.x = __float2half_rn(v[u].z); h1.y = __float2half_rn(v[u].w);
                uint2 hu; hu.x = *(uint32_t*)&h0; hu.y = *(uint32_t*)&h1;
                *(uint2*)&g_w3h[(i0 + u * stride) * 4] = hu;
            }
        }
        return;
    }

    extern __shared__ char smy[];
    const uint32_t sA = smem_u32(smy);
    const uint32_t sX = sA + 32768;

    const int lane = tid & 31;
    const int wid  = tid >> 5;
    const int wm   = wid & 1;
    const int wn   = wid >> 1;
    const int dt   = blockIdx.x & 63;
    const int b    = blockIdx.x >> 6;

    #pragma unroll
    for (int i = 0; i < 8; ++i) {
        int id = tid + i * 256;
        int s = id >> 4, c = id & 15;
        cp_async16(sA + s * 256 + ((c ^ (s & 7)) << 4),
                   g_attnh + (size_t)(b * TT + s) * TT + c * 8);
    }
    CP_COMMIT();

    #pragma unroll
    for (int i = 0; i < 16; ++i) {
        int id = tid + i * 256;
        int s = id >> 5, q = id & 31;
        float4 v = *(const float4*)&x1[(size_t)(b * TT + s) * DD + dt * 128 + q * 4];
        __half2 p0, p1;
        p0.x = __float2half_rn(v.x); p0.y = __float2half_rn(v.y);
        p1.x = __float2half_rn(v.z); p1.y = __float2half_rn(v.w);
        uint2 u; u.x = *(uint32_t*)&p0; u.y = *(uint32_t*)&p1;
        int c = q >> 1, h = q & 1;
        *(uint2*)(smy + 32768 + s * 256 + ((c ^ (s & 7)) << 4) + h * 8) = u;
    }
    CP_WAIT0();
    __syncthreads();

    float acc[4][4][4];
    #pragma unroll
    for (int a = 0; a < 4; ++a)
        #pragma unroll
        for (int bq = 0; bq < 4; ++bq)
            #pragma unroll
            for (int c = 0; c < 4; ++c) acc[a][bq][c] = 0.f;

    const int r_lane = (lane & 7) + ((lane >> 3) & 1) * 8;
    const int c_lane = lane >> 4;

    #pragma unroll
    for (int s16 = 0; s16 < 8; ++s16) {
        uint32_t af[4][4];
        #pragma unroll
        for (int mf = 0; mf < 4; ++mf) {
            int t = wm * 64 + mf * 16 + r_lane;
            int c = s16 * 2 + c_lane;
            ldsm4(af[mf], sA + t * 256 + ((c ^ (t & 7)) << 4));
        }
        #pragma unroll
        for (int nf2 = 0; nf2 < 2; ++nf2) {
            int srow = s16 * 16 + r_lane;
            int c = wn * 4 + nf2 * 2 + c_lane;
            uint32_t bt[4];
            ldsm4t(bt, sX + srow * 256 + ((c ^ (srow & 7)) << 4));
            #pragma unroll
            for (int mf = 0; mf < 4; ++mf) {
                mma16816h(acc[mf][nf2 * 2 + 0], af[mf], bt[0], bt[1]);
                mma16816h(acc[mf][nf2 * 2 + 1], af[mf], bt[2], bt[3]);
            }
        }
    }

    const int r_ep  = lane >> 2;
    const int cpair = (lane & 3) * 2;
    #pragma unroll
    for (int mf = 0; mf < 4; ++mf) {
        #pragma unroll
        for (int nf = 0; nf < 4; ++nf) {
            int t = wm * 64 + mf * 16 + r_ep;
            int d = dt * 128 + wn * 32 + nf * 8 + cpair;
            __half2 h0, h1;
            h0.x = __float2half_rn(acc[mf][nf][0]);
            h0.y = __float2half_rn(acc[mf][nf][1]);
            h1.x = __float2half_rn(acc[mf][nf][2]);
            h1.y = __float2half_rn(acc[mf][nf][3]);
            *(__half2*)&g_yh[(size_t)(b * TT + t) * DD + d]       = h0;
            *(__half2*)&g_yh[(size_t)(b * TT + t + 8) * DD + d]   = h1;
        }
    }
}

// =============================================================================
// K4 v6: out[m,g] = sum_k y[m,k] w3[g,k] + rs[m] b3[g]
// R15 tiling (128x128, 256 thr, 2m x 4n, 2 CTAs/SM) with a minimal-issue
// mainloop: kt unrolled x4 (compile-time stage bases), ldsm offsets
// precomputed (12 invariant regs), cp.async via striding pointers with
// precomputed swizzled dst offsets, loads issued right after the barrier.
// =============================================================================
#define STAGE_BYTES 16384
#define NSTG 4
#define SMEM_K4 (NSTG * STAGE_BYTES)
#define OFF_B 8192

__global__ __launch_bounds__(256, 2) void k_out_tc(
    const float* __restrict__ b3, float* __restrict__ out)
{
    extern __shared__ char smem[];
    const uint32_t sb = smem_u32(smem);
    const int tid  = threadIdx.x;
    const int lane = tid & 31;
    const int wid  = tid >> 5;
    const int wm   = wid & 1;          // 2 warps in m (64 rows each)
    const int wn   = wid >> 1;         // 4 warps in n (32 cols each)
    const int rb   = blockIdx.x;       // 0..15
    const int nb   = blockIdx.y;       // 0..31

    // ---- precomputed cp.async plumbing ----
    const __half* aB = g_yh  + (size_t)rb * 128 * DD;
    const __half* bB = g_w3h + (size_t)nb * 128 * DD;
    const int iA0 = tid, iA1 = 256 + tid;        // A chunk ids (0..511)
    const int rA0c = iA0 >> 2, cA0 = iA0 & 3;
    const int rA1c = iA1 >> 2, cA1 = iA1 & 3;
    const uint32_t dA0 = rA0c * 64 + ((cA0 ^ ((rA0c >> 1) & 3)) << 4);
    const uint32_t dA1 = rA1c * 64 + ((cA1 ^ ((rA1c >> 1) & 3)) << 4);
    const uint32_t dB0 = OFF_B + dA0;            // B uses same id mapping (rows 0..127)
    const uint32_t dB1 = OFF_B + dA1;
    const __half* pA0 = aB + (size_t)rA0c * DD + cA0 * 8;
    const __half* pA1 = aB + (size_t)rA1c * DD + cA1 * 8;
    const __half* pB0 = bB + (size_t)rA0c * DD + cA0 * 8;
    const __half* pB1 = bB + (size_t)rA1c * DD + cA1 * 8;

    auto issue = [&](uint32_t sbase) {
        cp_async16(sbase + dA0, pA0);
        cp_async16(sbase + dA1, pA1);
        cp_async16(sbase + dB0, pB0);
        cp_async16(sbase + dB1, pB1);
        pA0 += 32; pA1 += 32; pB0 += 32; pB1 += 32;
    };

    // ---- precomputed ldsm offsets (loop-invariant) ----
    const int r_lane = (lane & 7) + ((lane >> 3) & 1) * 8;
    const int c_lane = lane >> 4;
    uint32_t aoff[4][2], boff[2][2];
    #pragma unroll
    for (int mf = 0; mf < 4; ++mf) {
        int ra = wm * 64 + mf * 16 + r_lane;
        #pragma unroll
        for (int ks = 0; ks < 2; ++ks)
            aoff[mf][ks] = ra * 64 + (((2 * ks + c_lane) ^ ((ra >> 1) & 3)) << 4);
    }
    #pragma unroll
    for (int f = 0; f < 2; ++f) {
        int rn = wn * 32 + f * 16 + r_lane;
        #pragma unroll
        for (int ks = 0; ks < 2; ++ks)
            boff[f][ks] = OFF_B + rn * 64 + (((2 * ks + c_lane) ^ ((rn >> 1) & 3)) << 4);
    }

    float acc[4][4][4];
    #pragma unroll
    for (int a = 0; a < 4; ++a)
        #pragma unroll
        for (int b2 = 0; b2 < 4; ++b2)
            #pragma unroll
            for (int c = 0; c < 4; ++c) acc[a][b2][c] = 0.f;

    issue(sb);                     CP_COMMIT();
    issue(sb + STAGE_BYTES);       CP_COMMIT();
    issue(sb + 2 * STAGE_BYTES);   CP_COMMIT();

    for (int kt4 = 0; kt4 < 64; ++kt4) {
        #pragma unroll
        for (int st = 0; st < 4; ++st) {
            CP_WAIT2();
            __syncthreads();
            // issue next load (targets stage (st+3)&3, disjoint from stage st)
            if (kt4 * 4 + st + 3 < 256) issue(sb + ((st + 3) & 3) * STAGE_BYTES);
            CP_COMMIT();

            const uint32_t sbase = sb + st * STAGE_BYTES;
            #pragma unroll
            for (int ks = 0; ks < 2; ++ks) {
                uint32_t af[4][4], bf[2][4];
                #pragma unroll
                for (int mf = 0; mf < 4; ++mf)
                    ldsm4(af[mf], sbase + aoff[mf][ks]);
                #pragma unroll
                for (int nf2 = 0; nf2 < 2; ++nf2)
                    ldsm4(bf[nf2], sbase + boff[nf2][ks]);
                #pragma unroll
                for (int nf2 = 0; nf2 < 2; ++nf2) {
                    #pragma unroll
                    for (int mf = 0; mf < 4; ++mf) {
                        #pragma unroll
                        for (int s = 0; s < 2; ++s)
                            mma16816h(acc[mf][nf2 * 2 + s], af[mf], bf[nf2][s], bf[nf2][s + 2]);
                    }
                }
            }
        }
    }

    // ---- epilogue: out = acc + rs[m]*b3[g] ----
    const int r_ep  = lane >> 2;
    const int cpair = (lane & 3) * 2;

    float rsv[4][2];
    #pragma unroll
    for (int mf = 0; mf < 4; ++mf) {
        int row = rb * 128 + wm * 64 + mf * 16 + r_ep;
        rsv[mf][0] = g_rs[row];
        rsv[mf][1] = g_rs[row + 8];
    }
    float b3v[4][2];
    #pragma unroll
    for (int nf = 0; nf < 4; ++nf) {
        int colg = nb * 128 + wn * 32 + nf * 8 + cpair;
        b3v[nf][0] = b3[colg];
        b3v[nf][1] = b3[colg + 1];
    }

    #pragma unroll
    for (int mf = 0; mf < 4; ++mf) {
        #pragma unroll
        for (int nf = 0; nf < 4; ++nf) {
            int row  = rb * 128 + wm * 64 + mf * 16 + r_ep;
            int colg = nb * 128 + wn * 32 + nf * 8 + cpair;
            float2 v0, v1;
            v0.x = acc[mf][nf][0] + rsv[mf][0] * b3v[nf][0];
            v0.y = acc[mf][nf][1] + rsv[mf][0] * b3v[nf][1];
            v1.x = acc[mf][nf][2] + rsv[mf][1] * b3v[nf][0];
            v1.y = acc[mf][nf][3] + rsv[mf][1] * b3v[nf][1];
            *(float2*)&out[(size_t)row * GG + colg]       = v0;
            *(float2*)&out[(size_t)(row + 8) * GG + colg] = v1;
        }
    }
}

// =============================================================================
extern "C" void kernel_launch(void* const* d_in, const int* in_sizes, int n_in,
                              void* d_out, int out_size)
{
    const float* x1 = (const float*)d_in[0];
    const float* x2 = (const float*)d_in[1];
    const float* w1 = (const float*)d_in[2];
    const float* b1 = (const float*)d_in[3];
    const float* w2 = (const float*)d_in[4];
    const float* b2 = (const float*)d_in[5];
    const float* w3 = (const float*)d_in[6];
    const float* b3 = (const float*)d_in[7];
    float* out = (float*)d_out;

    cudaFuncSetAttribute(k_out_tc, cudaFuncAttributeMaxDynamicSharedMemorySize, SMEM_K4);
    cudaFuncSetAttribute(k_y, cudaFuncAttributeMaxDynamicSharedMemorySize, SMEM_KY);
    cudaFuncSetAttribute(k_qk, cudaFuncAttributeMaxDynamicSharedMemorySize, QK_SMEM);

    k_qk<<<MM / 16, 256, QK_SMEM>>>(x1, x2, w1, b1, w2, b2);
    k_scores_softmax<<<BB, 128>>>();
    k_y<<<1024 + NSPLIT, 256, SMEM_KY>>>(x1, w3);
    k_out_tc<<<dim3(MM / 128, GG / 128), 256, SMEM_K4>>>(b3, out);
}